// round 2
// baseline (speedup 1.0000x reference)
#include <cuda_runtime.h>
#include <math.h>

#define B_ 4
#define T_ 2048
#define C_ 1024
#define H_ 16
#define D_ 64

// Scratch (allocation-free rule: __device__ globals)
__device__ float g_qkv[(size_t)B_ * T_ * 3 * C_];   // [B*T, 3C]  (q | k | v)
__device__ float g_attn[(size_t)B_ * T_ * C_];      // [B*T, C]   attention output

// ----------------------------------------------------------------------------
// SGEMM:  C[m,n] = sum_k A[m,k] * Bw[n,k]  (+ bias[n])
// A: [M,K] row-major, Bw: [N,K] row-major (both K-contiguous — "TN" gemm)
// Tiles: BM=BN=128, BK=16, 256 threads, 8x8 per-thread register tile.
// Assumes M%128==0, N%128==0, K%16==0 (true for all three uses here).
// ----------------------------------------------------------------------------
__global__ __launch_bounds__(256) void sgemm_tn(
    const float* __restrict__ A, const float* __restrict__ Bw,
    const float* __restrict__ bias, float* __restrict__ Cmat,
    int M, int N, int K)
{
    const int BM = 128, BN = 128, BK = 16;
    __shared__ float As[BK][BM + 4];
    __shared__ float Bs[BK][BN + 4];

    int tid = threadIdx.x;
    int tx = tid & 15;        // 0..15  -> N direction
    int ty = tid >> 4;        // 0..15  -> M direction
    int bm = blockIdx.y * BM;
    int bn = blockIdx.x * BN;

    const float* Ab = A  + (size_t)bm * K;
    const float* Bb = Bw + (size_t)bn * K;

    float acc[8][8];
#pragma unroll
    for (int i = 0; i < 8; i++)
#pragma unroll
        for (int j = 0; j < 8; j++) acc[i][j] = 0.f;

    for (int k0 = 0; k0 < K; k0 += BK) {
        // 128 rows x 16 cols = 512 float4s; 256 threads x 2
#pragma unroll
        for (int it = 0; it < 2; it++) {
            int idx = tid + it * 256;
            int r  = idx >> 2;            // 0..127
            int c4 = (idx & 3) << 2;      // 0,4,8,12
            float4 a = *(const float4*)(Ab + (size_t)r * K + k0 + c4);
            As[c4 + 0][r] = a.x; As[c4 + 1][r] = a.y;
            As[c4 + 2][r] = a.z; As[c4 + 3][r] = a.w;
            float4 b = *(const float4*)(Bb + (size_t)r * K + k0 + c4);
            Bs[c4 + 0][r] = b.x; Bs[c4 + 1][r] = b.y;
            Bs[c4 + 2][r] = b.z; Bs[c4 + 3][r] = b.w;
        }
        __syncthreads();

#pragma unroll
        for (int k = 0; k < BK; k++) {
            float ra[8], rb[8];
#pragma unroll
            for (int i = 0; i < 8; i++) ra[i] = As[k][ty * 8 + i];
#pragma unroll
            for (int j = 0; j < 8; j++) rb[j] = Bs[k][tx * 8 + j];
#pragma unroll
            for (int i = 0; i < 8; i++)
#pragma unroll
                for (int j = 0; j < 8; j++)
                    acc[i][j] += ra[i] * rb[j];
        }
        __syncthreads();
    }

    float bv[8];
#pragma unroll
    for (int j = 0; j < 8; j++) bv[j] = bias ? bias[bn + tx * 8 + j] : 0.f;

#pragma unroll
    for (int i = 0; i < 8; i++) {
        size_t row = (size_t)(bm + ty * 8 + i);
        float* cp = Cmat + row * N + bn + tx * 8;
#pragma unroll
        for (int j = 0; j < 8; j++) cp[j] = acc[i][j] + bv[j];
    }
}

// ----------------------------------------------------------------------------
// Flash attention (fp32, causal). One CTA per (b, h, 64-row q tile).
// qkv layout: [B*T, 3C]; q cols [h*D, h*D+64), k at +C, v at +2C.
// Online softmax; only the diagonal KV tile applies the causal mask; tiles
// strictly above the diagonal are skipped entirely.
// ----------------------------------------------------------------------------
__global__ __launch_bounds__(256) void flash_attn_kernel(
    const float* __restrict__ qkv, float* __restrict__ out)
{
    const int BM = 64, BN = 64;
    const int LD = D_ + 4;   // 68: padded stride
    extern __shared__ float sm[];
    float* Qs = sm;                    // [BM][LD]
    float* Ks = Qs + BM * LD;          // [BN][LD]
    float* Vs = Ks + BN * LD;          // [BN][LD]
    float* Ps = Vs + BN * LD;          // [BM][LD] (uses BN<=LD cols)

    int tid = threadIdx.x;
    int tx = tid & 15;     // col group (4 cols)
    int ty = tid >> 4;     // row group (4 rows)
    int q0 = blockIdx.x * BM;
    int bh = blockIdx.y;
    int b = bh >> 4, h = bh & 15;

    // Load Q tile (64x64 floats, float4-vectorized)
    const float* qbase = qkv + (size_t)(b * T_ + q0) * (3 * C_) + h * D_;
    for (int i = tid; i < BM * (D_ / 4); i += 256) {
        int r = i >> 4, c = (i & 15) << 2;
        *(float4*)(Qs + r * LD + c) = *(const float4*)(qbase + (size_t)r * (3 * C_) + c);
    }

    float m_i[4], l_i[4], o[4][4];
#pragma unroll
    for (int i = 0; i < 4; i++) {
        m_i[i] = -INFINITY; l_i[i] = 0.f;
#pragma unroll
        for (int j = 0; j < 4; j++) o[i][j] = 0.f;
    }

    const float scale = 0.125f;  // 1/sqrt(64)

    for (int k0 = 0; k0 <= q0; k0 += BN) {
        __syncthreads();  // protect Ks/Vs/Ps from prev-iter readers (also fences Q load on iter 0)

        const float* kbase = qkv + (size_t)(b * T_ + k0) * (3 * C_) + C_ + h * D_;
        for (int i = tid; i < BN * (D_ / 4); i += 256) {
            int r = i >> 4, c = (i & 15) << 2;
            *(float4*)(Ks + r * LD + c) = *(const float4*)(kbase + (size_t)r * (3 * C_) + c);
            *(float4*)(Vs + r * LD + c) = *(const float4*)(kbase + C_ + (size_t)r * (3 * C_) + c);
        }
        __syncthreads();

        // S = scale * Q K^T  (per-thread 4x4 of 64x64)
        float s[4][4];
#pragma unroll
        for (int i = 0; i < 4; i++)
#pragma unroll
            for (int j = 0; j < 4; j++) s[i][j] = 0.f;

#pragma unroll 4
        for (int k = 0; k < D_; k++) {
            float qa[4], kb[4];
#pragma unroll
            for (int i = 0; i < 4; i++) qa[i] = Qs[(ty * 4 + i) * LD + k];
#pragma unroll
            for (int j = 0; j < 4; j++) kb[j] = Ks[(tx * 4 + j) * LD + k];
#pragma unroll
            for (int i = 0; i < 4; i++)
#pragma unroll
                for (int j = 0; j < 4; j++) s[i][j] += qa[i] * kb[j];
        }
#pragma unroll
        for (int i = 0; i < 4; i++)
#pragma unroll
            for (int j = 0; j < 4; j++) s[i][j] *= scale;

        if (k0 == q0) {  // diagonal tile: mask cols > rows
#pragma unroll
            for (int i = 0; i < 4; i++)
#pragma unroll
                for (int j = 0; j < 4; j++)
                    if (tx * 4 + j > ty * 4 + i) s[i][j] = -INFINITY;
        }

        // online softmax per row (reduce across the 16 tx threads; they occupy
        // lanes (ty&1)*16 + tx, so xor 1,2,4,8 stays within the row group)
#pragma unroll
        for (int i = 0; i < 4; i++) {
            float m = fmaxf(fmaxf(s[i][0], s[i][1]), fmaxf(s[i][2], s[i][3]));
            m = fmaxf(m, __shfl_xor_sync(0xffffffffu, m, 1));
            m = fmaxf(m, __shfl_xor_sync(0xffffffffu, m, 2));
            m = fmaxf(m, __shfl_xor_sync(0xffffffffu, m, 4));
            m = fmaxf(m, __shfl_xor_sync(0xffffffffu, m, 8));
            float mnew = fmaxf(m_i[i], m);
            float corr = __expf(m_i[i] - mnew);
            float ps = 0.f;
#pragma unroll
            for (int j = 0; j < 4; j++) {
                s[i][j] = __expf(s[i][j] - mnew);
                ps += s[i][j];
            }
            ps += __shfl_xor_sync(0xffffffffu, ps, 1);
            ps += __shfl_xor_sync(0xffffffffu, ps, 2);
            ps += __shfl_xor_sync(0xffffffffu, ps, 4);
            ps += __shfl_xor_sync(0xffffffffu, ps, 8);
            l_i[i] = l_i[i] * corr + ps;
            m_i[i] = mnew;
#pragma unroll
            for (int j = 0; j < 4; j++) o[i][j] *= corr;
        }

        // stage P to smem for the PV gemm
#pragma unroll
        for (int i = 0; i < 4; i++) {
            float4 pv = make_float4(s[i][0], s[i][1], s[i][2], s[i][3]);
            *(float4*)(Ps + (ty * 4 + i) * LD + tx * 4) = pv;
        }
        __syncthreads();

        // O += P @ V
#pragma unroll 4
        for (int kc = 0; kc < BN; kc++) {
            float pa[4];
#pragma unroll
            for (int i = 0; i < 4; i++) pa[i] = Ps[(ty * 4 + i) * LD + kc];
            float4 vv = *(const float4*)(Vs + kc * LD + tx * 4);
            float vb[4] = {vv.x, vv.y, vv.z, vv.w};
#pragma unroll
            for (int i = 0; i < 4; i++)
#pragma unroll
                for (int j = 0; j < 4; j++) o[i][j] += pa[i] * vb[j];
        }
    }

    // epilogue: out[b, q, h*D + d] = O / l   (layout [B*T, C])
#pragma unroll
    for (int i = 0; i < 4; i++) {
        float inv = 1.f / l_i[i];
        size_t row = (size_t)(b * T_ + q0 + ty * 4 + i);
        float4 r = make_float4(o[i][0] * inv, o[i][1] * inv, o[i][2] * inv, o[i][3] * inv);
        *(float4*)(out + row * C_ + h * D_ + tx * 4) = r;
    }
}

// ----------------------------------------------------------------------------
extern "C" void kernel_launch(void* const* d_in, const int* in_sizes, int n_in,
                              void* d_out, int out_size)
{
    const float* x     = (const float*)d_in[0];
    const float* w_qkv = (const float*)d_in[1];
    const float* w_out = (const float*)d_in[2];
    const float* b_out = (const float*)d_in[3];
    float* out = (float*)d_out;

    float *qkv_p = nullptr, *attn_p = nullptr;
    cudaGetSymbolAddress((void**)&qkv_p, g_qkv);
    cudaGetSymbolAddress((void**)&attn_p, g_attn);

    const int M = B_ * T_;

    // 1) qkv = x @ w_qkv^T   [8192, 3072]
    {
        dim3 grid((3 * C_) / 128, M / 128);
        sgemm_tn<<<grid, 256>>>(x, w_qkv, nullptr, qkv_p, M, 3 * C_, C_);
    }

    // 2) flash attention -> g_attn [8192, 1024]
    {
        const int smem = 4 * 64 * (D_ + 4) * (int)sizeof(float);  // 69632 B
        cudaFuncSetAttribute(flash_attn_kernel,
                             cudaFuncAttributeMaxDynamicSharedMemorySize, smem);
        dim3 grid(T_ / 64, B_ * H_);
        flash_attn_kernel<<<grid, 256, smem>>>(qkv_p, attn_p);
    }

    // 3) out = g_attn @ w_out^T + b_out   [8192, 1024]
    {
        dim3 grid(C_ / 128, M / 128);
        sgemm_tn<<<grid, 256>>>(attn_p, w_out, b_out, out, M, C_, C_);
    }
}

// round 5
// speedup vs baseline: 1.4690x; 1.4690x over previous
#include <cuda_runtime.h>
#include <cstdint>
#include <math.h>

#define B_ 4
#define T_ 2048
#define C_ 1024
#define H_ 16
#define D_ 64

// Scratch (__device__ globals; allocation-free rule)
__device__ float g_qkv[(size_t)B_ * T_ * 3 * C_];    // [B*T, 3C]
__device__ float g_attn[(size_t)B_ * T_ * C_];       // [B*T, C] (tf32-rounded)
__device__ float g_xr[(size_t)B_ * T_ * C_];         // tf32-rounded x
__device__ float g_wqkvr[(size_t)3 * C_ * C_];       // tf32-rounded w_qkv
__device__ float g_woutr[(size_t)C_ * C_];           // tf32-rounded w_out

// ---------------------------------------------------------------------------
__device__ __forceinline__ uint32_t smem_u32(const void* p) {
    uint32_t a;
    asm("{ .reg .u64 t; cvta.to.shared.u64 t, %1; cvt.u32.u64 %0, t; }" : "=r"(a) : "l"(p));
    return a;
}

__device__ __forceinline__ void cp_async16(uint32_t s, const void* g) {
    asm volatile("cp.async.cg.shared.global [%0], [%1], 16;" :: "r"(s), "l"(g));
}

__device__ __forceinline__ float round_tf32(float x) {
    uint32_t u;
    asm("cvt.rna.tf32.f32 %0, %1;" : "=r"(u) : "f"(x));
    return __uint_as_float(u);
}

// ---------------------------------------------------------------------------
// tf32 RTN rounding pre-pass (removes truncation bias)
// ---------------------------------------------------------------------------
__global__ __launch_bounds__(256) void round_tf32_kernel(
    const float4* __restrict__ in, float4* __restrict__ out, int n4)
{
    int i = blockIdx.x * blockDim.x + threadIdx.x;
    if (i >= n4) return;
    float4 v = in[i];
    v.x = round_tf32(v.x); v.y = round_tf32(v.y);
    v.z = round_tf32(v.z); v.w = round_tf32(v.w);
    out[i] = v;
}

// ---------------------------------------------------------------------------
// mma.sync tf32 GEMM:  C[m,n] = sum_k A[m,k]*Bw[n,k] (+bias[n])
// A:[M,K], Bw:[N,K] row-major fp32 (pre-rounded to tf32). Portable PTX
// (compute_103-safe; no tcgen05). BM=BN=128, BK=32, 3-stage cp.async,
// 8 warps, warp tile 64x32 via m16n8k8.
// ---------------------------------------------------------------------------
#define G_BM 128
#define G_BN 128
#define G_BK 32
#define G_ST 3
#define G_LD (G_BK + 4)                       // 36 floats: conflict-free + 16B-aligned rows
#define STAGE_FLOATS ((G_BM + G_BN) * G_LD)   // 9216 floats = 36864 B
#define G_SMEM (G_ST * STAGE_FLOATS * 4)      // 110592 B

__device__ __forceinline__ void mma_tf32(float c[4], uint32_t a0, uint32_t a1,
                                         uint32_t a2, uint32_t a3,
                                         uint32_t b0, uint32_t b1)
{
    asm volatile(
        "mma.sync.aligned.m16n8k8.row.col.f32.tf32.tf32.f32 "
        "{%0,%1,%2,%3}, {%4,%5,%6,%7}, {%8,%9}, {%0,%1,%2,%3};"
        : "+f"(c[0]), "+f"(c[1]), "+f"(c[2]), "+f"(c[3])
        : "r"(a0), "r"(a1), "r"(a2), "r"(a3), "r"(b0), "r"(b1));
}

__global__ __launch_bounds__(256, 1) void gemm_mma_tf32(
    const float* __restrict__ A, const float* __restrict__ Bw,
    const float* __restrict__ bias, float* __restrict__ Cmat,
    int N, int K)
{
    extern __shared__ float sm[];
    const int tid = threadIdx.x;
    const int lane = tid & 31, wid = tid >> 5;
    const int warp_m = (wid >> 2) * 64;   // 0 / 64
    const int warp_n = (wid & 3) * 32;    // 0 / 32 / 64 / 96
    const int bm = blockIdx.y * G_BM;
    const int bn = blockIdx.x * G_BN;
    const int nk = K / G_BK;

    const int lm = lane >> 2;   // 0..7
    const int lk = lane & 3;    // 0..3

    float c[4][4][4];
#pragma unroll
    for (int mf = 0; mf < 4; mf++)
#pragma unroll
        for (int nf = 0; nf < 4; nf++)
#pragma unroll
            for (int r = 0; r < 4; r++) c[mf][nf][r] = 0.f;

    const float* Ab = A + (size_t)bm * K;
    const float* Bb = Bw + (size_t)bn * K;
    const int lrow = tid >> 3;        // 0..31 row step per iteration group
    const int lseg = tid & 7;         // 16B segment within 128B row chunk

    uint32_t smbase = smem_u32(sm);

    // stage filler: A rows [0,128) + B rows [0,128), BK=32 floats = 8x16B per row
    auto issue_stage = [&](int chunk, int s) {
        uint32_t As = smbase + s * STAGE_FLOATS * 4;
        uint32_t Bs = As + G_BM * G_LD * 4;
        const float* Ag = Ab + (size_t)chunk * G_BK;
        const float* Bg = Bb + (size_t)chunk * G_BK;
#pragma unroll
        for (int it = 0; it < 4; it++) {
            int row = lrow + it * 32;
            cp_async16(As + (row * G_LD + lseg * 4) * 4, Ag + (size_t)row * K + lseg * 4);
        }
#pragma unroll
        for (int it = 0; it < 4; it++) {
            int row = lrow + it * 32;
            cp_async16(Bs + (row * G_LD + lseg * 4) * 4, Bg + (size_t)row * K + lseg * 4);
        }
    };

    // prologue: stages 0..G_ST-2
#pragma unroll
    for (int s = 0; s < G_ST - 1; s++) {
        issue_stage(s, s);
        asm volatile("cp.async.commit_group;" ::: "memory");
    }

    for (int i = 0; i < nk; i++) {
        if (i + G_ST - 1 < nk) issue_stage(i + G_ST - 1, (i + G_ST - 1) % G_ST);
        asm volatile("cp.async.commit_group;" ::: "memory");
        asm volatile("cp.async.wait_group 2;" ::: "memory");
        __syncthreads();

        const float* As = sm + (i % G_ST) * STAGE_FLOATS;
        const float* Bs = As + G_BM * G_LD;

#pragma unroll
        for (int ks = 0; ks < 4; ks++) {
            const int k0 = ks * 8;
            uint32_t a[4][4], b[4][2];
#pragma unroll
            for (int mf = 0; mf < 4; mf++) {
                int m = warp_m + mf * 16 + lm;
                a[mf][0] = __float_as_uint(As[m * G_LD + k0 + lk]);
                a[mf][1] = __float_as_uint(As[(m + 8) * G_LD + k0 + lk]);
                a[mf][2] = __float_as_uint(As[m * G_LD + k0 + lk + 4]);
                a[mf][3] = __float_as_uint(As[(m + 8) * G_LD + k0 + lk + 4]);
            }
#pragma unroll
            for (int nf = 0; nf < 4; nf++) {
                int n = warp_n + nf * 8 + lm;
                b[nf][0] = __float_as_uint(Bs[n * G_LD + k0 + lk]);
                b[nf][1] = __float_as_uint(Bs[n * G_LD + k0 + lk + 4]);
            }
#pragma unroll
            for (int mf = 0; mf < 4; mf++)
#pragma unroll
                for (int nf = 0; nf < 4; nf++)
                    mma_tf32(c[mf][nf], a[mf][0], a[mf][1], a[mf][2], a[mf][3],
                             b[nf][0], b[nf][1]);
        }
        __syncthreads();
    }

    // epilogue: c0,c1 -> (m, n..n+1); c2,c3 -> (m+8, ...)
#pragma unroll
    for (int mf = 0; mf < 4; mf++) {
        int m = bm + warp_m + mf * 16 + lm;
#pragma unroll
        for (int nf = 0; nf < 4; nf++) {
            int n = bn + warp_n + nf * 8 + 2 * lk;
            float bx = 0.f, by = 0.f;
            if (bias) { bx = bias[n]; by = bias[n + 1]; }
            float* p0 = Cmat + (size_t)m * N + n;
            float* p1 = Cmat + (size_t)(m + 8) * N + n;
            *(float2*)p0 = make_float2(c[mf][nf][0] + bx, c[mf][nf][1] + by);
            *(float2*)p1 = make_float2(c[mf][nf][2] + bx, c[mf][nf][3] + by);
        }
    }
}

// ---------------------------------------------------------------------------
// Flash attention (fp32, causal) — validated in round 2; tf32-rounded epilogue
// ---------------------------------------------------------------------------
__global__ __launch_bounds__(256) void flash_attn_kernel(
    const float* __restrict__ qkv, float* __restrict__ out)
{
    const int BM = 64, BN = 64;
    const int LD = D_ + 4;
    extern __shared__ float sm[];
    float* Qs = sm;
    float* Ks = Qs + BM * LD;
    float* Vs = Ks + BN * LD;
    float* Ps = Vs + BN * LD;

    int tid = threadIdx.x;
    int tx = tid & 15;
    int ty = tid >> 4;
    int q0 = blockIdx.x * BM;
    int bh = blockIdx.y;
    int b = bh >> 4, h = bh & 15;

    const float* qbase = qkv + (size_t)(b * T_ + q0) * (3 * C_) + h * D_;
    for (int i = tid; i < BM * (D_ / 4); i += 256) {
        int r = i >> 4, c = (i & 15) << 2;
        *(float4*)(Qs + r * LD + c) = *(const float4*)(qbase + (size_t)r * (3 * C_) + c);
    }

    float m_i[4], l_i[4], o[4][4];
#pragma unroll
    for (int i = 0; i < 4; i++) {
        m_i[i] = -INFINITY; l_i[i] = 0.f;
#pragma unroll
        for (int j = 0; j < 4; j++) o[i][j] = 0.f;
    }

    const float scale = 0.125f;

    for (int k0 = 0; k0 <= q0; k0 += BN) {
        __syncthreads();

        const float* kbase = qkv + (size_t)(b * T_ + k0) * (3 * C_) + C_ + h * D_;
        for (int i = tid; i < BN * (D_ / 4); i += 256) {
            int r = i >> 4, c = (i & 15) << 2;
            *(float4*)(Ks + r * LD + c) = *(const float4*)(kbase + (size_t)r * (3 * C_) + c);
            *(float4*)(Vs + r * LD + c) = *(const float4*)(kbase + C_ + (size_t)r * (3 * C_) + c);
        }
        __syncthreads();

        float s[4][4];
#pragma unroll
        for (int i = 0; i < 4; i++)
#pragma unroll
            for (int j = 0; j < 4; j++) s[i][j] = 0.f;

#pragma unroll 4
        for (int k = 0; k < D_; k++) {
            float qa[4], kb[4];
#pragma unroll
            for (int i = 0; i < 4; i++) qa[i] = Qs[(ty * 4 + i) * LD + k];
#pragma unroll
            for (int j = 0; j < 4; j++) kb[j] = Ks[(tx * 4 + j) * LD + k];
#pragma unroll
            for (int i = 0; i < 4; i++)
#pragma unroll
                for (int j = 0; j < 4; j++) s[i][j] += qa[i] * kb[j];
        }
#pragma unroll
        for (int i = 0; i < 4; i++)
#pragma unroll
            for (int j = 0; j < 4; j++) s[i][j] *= scale;

        if (k0 == q0) {
#pragma unroll
            for (int i = 0; i < 4; i++)
#pragma unroll
                for (int j = 0; j < 4; j++)
                    if (tx * 4 + j > ty * 4 + i) s[i][j] = -INFINITY;
        }

#pragma unroll
        for (int i = 0; i < 4; i++) {
            float m = fmaxf(fmaxf(s[i][0], s[i][1]), fmaxf(s[i][2], s[i][3]));
            m = fmaxf(m, __shfl_xor_sync(0xffffffffu, m, 1));
            m = fmaxf(m, __shfl_xor_sync(0xffffffffu, m, 2));
            m = fmaxf(m, __shfl_xor_sync(0xffffffffu, m, 4));
            m = fmaxf(m, __shfl_xor_sync(0xffffffffu, m, 8));
            float mnew = fmaxf(m_i[i], m);
            float corr = __expf(m_i[i] - mnew);
            float ps = 0.f;
#pragma unroll
            for (int j = 0; j < 4; j++) {
                s[i][j] = __expf(s[i][j] - mnew);
                ps += s[i][j];
            }
            ps += __shfl_xor_sync(0xffffffffu, ps, 1);
            ps += __shfl_xor_sync(0xffffffffu, ps, 2);
            ps += __shfl_xor_sync(0xffffffffu, ps, 4);
            ps += __shfl_xor_sync(0xffffffffu, ps, 8);
            l_i[i] = l_i[i] * corr + ps;
            m_i[i] = mnew;
#pragma unroll
            for (int j = 0; j < 4; j++) o[i][j] *= corr;
        }

#pragma unroll
        for (int i = 0; i < 4; i++) {
            float4 pv = make_float4(s[i][0], s[i][1], s[i][2], s[i][3]);
            *(float4*)(Ps + (ty * 4 + i) * LD + tx * 4) = pv;
        }
        __syncthreads();

#pragma unroll 4
        for (int kc = 0; kc < BN; kc++) {
            float pa[4];
#pragma unroll
            for (int i = 0; i < 4; i++) pa[i] = Ps[(ty * 4 + i) * LD + kc];
            float4 vv = *(const float4*)(Vs + kc * LD + tx * 4);
            float vb[4] = {vv.x, vv.y, vv.z, vv.w};
#pragma unroll
            for (int i = 0; i < 4; i++)
#pragma unroll
                for (int j = 0; j < 4; j++) o[i][j] += pa[i] * vb[j];
        }
    }

#pragma unroll
    for (int i = 0; i < 4; i++) {
        float inv = 1.f / l_i[i];
        size_t row = (size_t)(b * T_ + q0 + ty * 4 + i);
        float4 r = make_float4(round_tf32(o[i][0] * inv), round_tf32(o[i][1] * inv),
                               round_tf32(o[i][2] * inv), round_tf32(o[i][3] * inv));
        *(float4*)(out + row * C_ + h * D_ + tx * 4) = r;
    }
}

// ---------------------------------------------------------------------------
extern "C" void kernel_launch(void* const* d_in, const int* in_sizes, int n_in,
                              void* d_out, int out_size)
{
    const float* x     = (const float*)d_in[0];
    const float* w_qkv = (const float*)d_in[1];
    const float* w_out = (const float*)d_in[2];
    const float* b_out = (const float*)d_in[3];
    float* out = (float*)d_out;

    float *qkv_p, *attn_p, *xr_p, *wqkvr_p, *woutr_p;
    cudaGetSymbolAddress((void**)&qkv_p, g_qkv);
    cudaGetSymbolAddress((void**)&attn_p, g_attn);
    cudaGetSymbolAddress((void**)&xr_p, g_xr);
    cudaGetSymbolAddress((void**)&wqkvr_p, g_wqkvr);
    cudaGetSymbolAddress((void**)&woutr_p, g_woutr);

    const int M = B_ * T_;

    // 0) tf32-round GEMM inputs
    {
        int n4x = (M * C_) / 4;
        round_tf32_kernel<<<(n4x + 255) / 256, 256>>>((const float4*)x, (float4*)xr_p, n4x);
        int n4w = (3 * C_ * C_) / 4;
        round_tf32_kernel<<<(n4w + 255) / 256, 256>>>((const float4*)w_qkv, (float4*)wqkvr_p, n4w);
        int n4o = (C_ * C_) / 4;
        round_tf32_kernel<<<(n4o + 255) / 256, 256>>>((const float4*)w_out, (float4*)woutr_p, n4o);
    }

    cudaFuncSetAttribute(gemm_mma_tf32, cudaFuncAttributeMaxDynamicSharedMemorySize, G_SMEM);

    // 1) qkv = x @ w_qkv^T  [8192, 3072]  (mma.sync tf32)
    {
        dim3 grid((3 * C_) / G_BN, M / G_BM);
        gemm_mma_tf32<<<grid, 256, G_SMEM>>>(xr_p, wqkvr_p, nullptr, qkv_p, 3 * C_, C_);
    }

    // 2) flash attention -> g_attn [8192, 1024]
    {
        const int smem = 4 * 64 * (D_ + 4) * (int)sizeof(float);
        cudaFuncSetAttribute(flash_attn_kernel,
                             cudaFuncAttributeMaxDynamicSharedMemorySize, smem);
        dim3 grid(T_ / 64, B_ * H_);
        flash_attn_kernel<<<grid, 256, smem>>>(qkv_p, attn_p);
    }

    // 3) out = g_attn @ w_out^T + b_out  [8192, 1024]  (mma.sync tf32)
    {
        dim3 grid(C_ / G_BN, M / G_BM);
        gemm_mma_tf32<<<grid, 256, G_SMEM>>>(attn_p, woutr_p, b_out, out, C_, C_);
    }
}

// round 8
// speedup vs baseline: 3.5149x; 2.3927x over previous
#include <cuda_runtime.h>
#include <cstdint>
#include <math.h>

#define B_ 4
#define T_ 2048
#define C_ 1024
#define H_ 16
#define D_ 64

// Scratch (__device__ globals; allocation-free rule)
__device__ float g_qkv[(size_t)B_ * T_ * 3 * C_];    // [B*T, 3C] (tf32-rounded)
__device__ float g_attn[(size_t)B_ * T_ * C_];       // [B*T, C] (tf32-rounded)
__device__ float g_xr[(size_t)B_ * T_ * C_];         // tf32-rounded x
__device__ float g_wqkvr[(size_t)3 * C_ * C_];       // tf32-rounded w_qkv
__device__ float g_woutr[(size_t)C_ * C_];           // tf32-rounded w_out

// ---------------------------------------------------------------------------
__device__ __forceinline__ uint32_t smem_u32(const void* p) {
    uint32_t a;
    asm("{ .reg .u64 t; cvta.to.shared.u64 t, %1; cvt.u32.u64 %0, t; }" : "=r"(a) : "l"(p));
    return a;
}

__device__ __forceinline__ void cp_async16(uint32_t s, const void* g) {
    asm volatile("cp.async.cg.shared.global [%0], [%1], 16;" :: "r"(s), "l"(g));
}

__device__ __forceinline__ float round_tf32(float x) {
    uint32_t u;
    asm("cvt.rna.tf32.f32 %0, %1;" : "=r"(u) : "f"(x));
    return __uint_as_float(u);
}

__device__ __forceinline__ void mma_tf32(float c[4], uint32_t a0, uint32_t a1,
                                         uint32_t a2, uint32_t a3,
                                         uint32_t b0, uint32_t b1)
{
    asm volatile(
        "mma.sync.aligned.m16n8k8.row.col.f32.tf32.tf32.f32 "
        "{%0,%1,%2,%3}, {%4,%5,%6,%7}, {%8,%9}, {%0,%1,%2,%3};"
        : "+f"(c[0]), "+f"(c[1]), "+f"(c[2]), "+f"(c[3])
        : "r"(a0), "r"(a1), "r"(a2), "r"(a3), "r"(b0), "r"(b1));
}

// ---------------------------------------------------------------------------
// tf32 RTN rounding pre-pass
// ---------------------------------------------------------------------------
__global__ __launch_bounds__(256) void round_tf32_kernel(
    const float4* __restrict__ in, float4* __restrict__ out, int n4)
{
    int i = blockIdx.x * blockDim.x + threadIdx.x;
    if (i >= n4) return;
    float4 v = in[i];
    v.x = round_tf32(v.x); v.y = round_tf32(v.y);
    v.z = round_tf32(v.z); v.w = round_tf32(v.w);
    out[i] = v;
}

// ---------------------------------------------------------------------------
// mma.sync tf32 GEMM (round 5 proven). Optional tf32-rounded output.
// ---------------------------------------------------------------------------
#define G_BM 128
#define G_BN 128
#define G_BK 32
#define G_ST 3
#define G_LD (G_BK + 4)
#define STAGE_FLOATS ((G_BM + G_BN) * G_LD)
#define G_SMEM (G_ST * STAGE_FLOATS * 4)

__global__ __launch_bounds__(256, 1) void gemm_mma_tf32(
    const float* __restrict__ A, const float* __restrict__ Bw,
    const float* __restrict__ bias, float* __restrict__ Cmat,
    int N, int K, int round_out)
{
    extern __shared__ float sm[];
    const int tid = threadIdx.x;
    const int lane = tid & 31, wid = tid >> 5;
    const int warp_m = (wid >> 2) * 64;
    const int warp_n = (wid & 3) * 32;
    const int bm = blockIdx.y * G_BM;
    const int bn = blockIdx.x * G_BN;
    const int nk = K / G_BK;

    const int lm = lane >> 2;
    const int lk = lane & 3;

    float c[4][4][4];
#pragma unroll
    for (int mf = 0; mf < 4; mf++)
#pragma unroll
        for (int nf = 0; nf < 4; nf++)
#pragma unroll
            for (int r = 0; r < 4; r++) c[mf][nf][r] = 0.f;

    const float* Ab = A + (size_t)bm * K;
    const float* Bb = Bw + (size_t)bn * K;
    const int lrow = tid >> 3;
    const int lseg = tid & 7;

    uint32_t smbase = smem_u32(sm);

    auto issue_stage = [&](int chunk, int s) {
        uint32_t As = smbase + s * STAGE_FLOATS * 4;
        uint32_t Bs = As + G_BM * G_LD * 4;
        const float* Ag = Ab + (size_t)chunk * G_BK;
        const float* Bg = Bb + (size_t)chunk * G_BK;
#pragma unroll
        for (int it = 0; it < 4; it++) {
            int row = lrow + it * 32;
            cp_async16(As + (row * G_LD + lseg * 4) * 4, Ag + (size_t)row * K + lseg * 4);
        }
#pragma unroll
        for (int it = 0; it < 4; it++) {
            int row = lrow + it * 32;
            cp_async16(Bs + (row * G_LD + lseg * 4) * 4, Bg + (size_t)row * K + lseg * 4);
        }
    };

#pragma unroll
    for (int s = 0; s < G_ST - 1; s++) {
        issue_stage(s, s);
        asm volatile("cp.async.commit_group;" ::: "memory");
    }

    for (int i = 0; i < nk; i++) {
        if (i + G_ST - 1 < nk) issue_stage(i + G_ST - 1, (i + G_ST - 1) % G_ST);
        asm volatile("cp.async.commit_group;" ::: "memory");
        asm volatile("cp.async.wait_group 2;" ::: "memory");
        __syncthreads();

        const float* As = sm + (i % G_ST) * STAGE_FLOATS;
        const float* Bs = As + G_BM * G_LD;

#pragma unroll
        for (int ks = 0; ks < 4; ks++) {
            const int k0 = ks * 8;
            uint32_t a[4][4], b[4][2];
#pragma unroll
            for (int mf = 0; mf < 4; mf++) {
                int m = warp_m + mf * 16 + lm;
                a[mf][0] = __float_as_uint(As[m * G_LD + k0 + lk]);
                a[mf][1] = __float_as_uint(As[(m + 8) * G_LD + k0 + lk]);
                a[mf][2] = __float_as_uint(As[m * G_LD + k0 + lk + 4]);
                a[mf][3] = __float_as_uint(As[(m + 8) * G_LD + k0 + lk + 4]);
            }
#pragma unroll
            for (int nf = 0; nf < 4; nf++) {
                int n = warp_n + nf * 8 + lm;
                b[nf][0] = __float_as_uint(Bs[n * G_LD + k0 + lk]);
                b[nf][1] = __float_as_uint(Bs[n * G_LD + k0 + lk + 4]);
            }
#pragma unroll
            for (int mf = 0; mf < 4; mf++)
#pragma unroll
                for (int nf = 0; nf < 4; nf++)
                    mma_tf32(c[mf][nf], a[mf][0], a[mf][1], a[mf][2], a[mf][3],
                             b[nf][0], b[nf][1]);
        }
        __syncthreads();
    }

#pragma unroll
    for (int mf = 0; mf < 4; mf++) {
        int m = bm + warp_m + mf * 16 + lm;
#pragma unroll
        for (int nf = 0; nf < 4; nf++) {
            int n = bn + warp_n + nf * 8 + 2 * lk;
            float bx = 0.f, by = 0.f;
            if (bias) { bx = bias[n]; by = bias[n + 1]; }
            float v0 = c[mf][nf][0] + bx, v1 = c[mf][nf][1] + by;
            float v2 = c[mf][nf][2] + bx, v3 = c[mf][nf][3] + by;
            if (round_out) {
                v0 = round_tf32(v0); v1 = round_tf32(v1);
                v2 = round_tf32(v2); v3 = round_tf32(v3);
            }
            float* p0 = Cmat + (size_t)m * N + n;
            float* p1 = Cmat + (size_t)(m + 8) * N + n;
            *(float2*)p0 = make_float2(v0, v1);
            *(float2*)p1 = make_float2(v2, v3);
        }
    }
}

// ---------------------------------------------------------------------------
// Flash attention with mma.sync tf32.
// BM=128 q-rows/CTA, BN=64 kv per iter, 8 warps (warp owns 16 q-rows).
// Q frags cached in regs; K double-buffered cp.async; V transposed in smem;
// P staged through smem. qkv is tf32-pre-rounded (gemm epilogue), so mma
// truncation is exact; P rounded with cvt.rna before PV.
// ---------------------------------------------------------------------------
#define FBM 128
#define FBN 64
#define FLD 68
#define KS_STAGE (64 * FLD)
#define VS_OFF (2 * KS_STAGE)
#define PS_OFF (VS_OFF + 64 * FLD)
#define FSMEM_FLOATS (PS_OFF + 128 * FLD)
#define FSMEM_BYTES (FSMEM_FLOATS * 4)     // 87040

__global__ __launch_bounds__(256, 1) void flash_mma_kernel(
    const float* __restrict__ qkv, float* __restrict__ out)
{
    extern __shared__ float sm[];
    float* Vs = sm + VS_OFF;
    float* Ps = sm + PS_OFF;

    const int tid = threadIdx.x, lane = tid & 31, wid = tid >> 5;
    const int lm = lane >> 2, lk = lane & 3;
    const int warp_m = wid * 16;
    const int qtile = gridDim.x - 1 - blockIdx.x;   // heavy tiles first
    const int q0 = qtile * FBM;
    const int bh = blockIdx.y;
    const int b = bh >> 4, h = bh & 15;
    const size_t rs = 3 * C_;

    const float* qptr = qkv + (size_t)(b * T_ + q0) * rs + h * D_;
    const float* kptr0 = qkv + (size_t)(b * T_) * rs + C_ + h * D_;
    const float* vptr0 = kptr0 + C_;

    uint32_t smb = smem_u32(sm);

    const int nit = q0 / FBN + 2;

    // K tile loader: 64 rows x 64 floats, coalesced cp.async
    auto load_k = [&](int it, int s) {
        const float* kg = kptr0 + (size_t)(it * FBN) * rs;
        uint32_t dst = smb + (uint32_t)(s * KS_STAGE) * 4;
        int seg = tid & 15, r0 = tid >> 4;
#pragma unroll
        for (int i = 0; i < 4; i++) {
            int r = r0 + i * 16;
            cp_async16(dst + (uint32_t)(r * FLD + seg * 4) * 4,
                       kg + (size_t)r * rs + seg * 4);
        }
    };

    load_k(0, 0);
    asm volatile("cp.async.commit_group;" ::: "memory");

    // Stage Q into Ps region (coalesced), then load Q fragments
    {
        int seg = tid & 15, r0 = tid >> 4;
#pragma unroll
        for (int i = 0; i < 8; i++) {
            int r = r0 + i * 16;
            *(float4*)(Ps + r * FLD + seg * 4) =
                *(const float4*)(qptr + (size_t)r * rs + seg * 4);
        }
    }
    __syncthreads();
    uint32_t qf[8][4];
#pragma unroll
    for (int ks = 0; ks < 8; ks++) {
        int m0 = warp_m + lm, k0 = ks * 8;
        qf[ks][0] = __float_as_uint(Ps[m0 * FLD + k0 + lk]);
        qf[ks][1] = __float_as_uint(Ps[(m0 + 8) * FLD + k0 + lk]);
        qf[ks][2] = __float_as_uint(Ps[m0 * FLD + k0 + lk + 4]);
        qf[ks][3] = __float_as_uint(Ps[(m0 + 8) * FLD + k0 + lk + 4]);
    }

    float mI0 = -INFINITY, mI1 = -INFINITY, lI0 = 0.f, lI1 = 0.f;
    float oacc[8][4];
#pragma unroll
    for (int nf = 0; nf < 8; nf++)
#pragma unroll
        for (int r = 0; r < 4; r++) oacc[nf][r] = 0.f;

    const float scl = 0.125f;   // 1/sqrt(64)

    for (int it = 0; it < nit; it++) {
        const int s = it & 1;
        if (it + 1 < nit) {
            load_k(it + 1, s ^ 1);
            asm volatile("cp.async.commit_group;" ::: "memory");
            asm volatile("cp.async.wait_group 1;" ::: "memory");
        } else {
            asm volatile("cp.async.wait_group 0;" ::: "memory");
        }
        __syncthreads();   // K[s] ready; prev iter's Ps/Vs consumers done

        // V tile -> regs (latency overlapped with S-mma below)
        const float* vg = vptr0 + (size_t)(it * FBN) * rs;
        const int kv = tid & 63, db = tid >> 6;
        float4 vbuf[4];
#pragma unroll
        for (int j = 0; j < 4; j++)
            vbuf[j] = *(const float4*)(vg + (size_t)kv * rs + db * 16 + j * 4);

        // S = Q K^T
        float sa[8][4];
#pragma unroll
        for (int nf = 0; nf < 8; nf++)
#pragma unroll
            for (int r = 0; r < 4; r++) sa[nf][r] = 0.f;

        const float* Kst = sm + s * KS_STAGE;
#pragma unroll
        for (int ks = 0; ks < 8; ks++) {
            uint32_t bf[8][2];
#pragma unroll
            for (int nf = 0; nf < 8; nf++) {
                int n = nf * 8 + lm;
                bf[nf][0] = __float_as_uint(Kst[n * FLD + ks * 8 + lk]);
                bf[nf][1] = __float_as_uint(Kst[n * FLD + ks * 8 + lk + 4]);
            }
#pragma unroll
            for (int nf = 0; nf < 8; nf++)
                mma_tf32(sa[nf], qf[ks][0], qf[ks][1], qf[ks][2], qf[ks][3],
                         bf[nf][0], bf[nf][1]);
        }

        // store V transposed (Vs[d][kv]) — loads have drained by now
#pragma unroll
        for (int j = 0; j < 4; j++) {
            Vs[(db * 16 + j * 4 + 0) * FLD + kv] = vbuf[j].x;
            Vs[(db * 16 + j * 4 + 1) * FLD + kv] = vbuf[j].y;
            Vs[(db * 16 + j * 4 + 2) * FLD + kv] = vbuf[j].z;
            Vs[(db * 16 + j * 4 + 3) * FLD + kv] = vbuf[j].w;
        }

        // scale + causal mask (only last two tiles can be masked)
        const int k0g = it * FBN;
        if (it >= nit - 2) {
#pragma unroll
            for (int nf = 0; nf < 8; nf++)
#pragma unroll
                for (int r = 0; r < 4; r++) {
                    int i_loc = warp_m + lm + ((r >= 2) ? 8 : 0);
                    int j_loc = nf * 8 + 2 * lk + (r & 1);
                    float v = sa[nf][r] * scl;
                    sa[nf][r] = (k0g + j_loc > q0 + i_loc) ? -INFINITY : v;
                }
        } else {
#pragma unroll
            for (int nf = 0; nf < 8; nf++)
#pragma unroll
                for (int r = 0; r < 4; r++) sa[nf][r] *= scl;
        }

        // online softmax (rows lm -> regs 0,1 ; lm+8 -> regs 2,3)
        float mx0 = -INFINITY, mx1 = -INFINITY;
#pragma unroll
        for (int nf = 0; nf < 8; nf++) {
            mx0 = fmaxf(mx0, fmaxf(sa[nf][0], sa[nf][1]));
            mx1 = fmaxf(mx1, fmaxf(sa[nf][2], sa[nf][3]));
        }
        mx0 = fmaxf(mx0, __shfl_xor_sync(0xffffffffu, mx0, 1));
        mx0 = fmaxf(mx0, __shfl_xor_sync(0xffffffffu, mx0, 2));
        mx1 = fmaxf(mx1, __shfl_xor_sync(0xffffffffu, mx1, 1));
        mx1 = fmaxf(mx1, __shfl_xor_sync(0xffffffffu, mx1, 2));

        float mn0 = fmaxf(mI0, mx0), mn1 = fmaxf(mI1, mx1);
        float c0 = __expf(mI0 - mn0), c1 = __expf(mI1 - mn1);
        float sum0 = 0.f, sum1 = 0.f;
#pragma unroll
        for (int nf = 0; nf < 8; nf++) {
            sa[nf][0] = __expf(sa[nf][0] - mn0);
            sa[nf][1] = __expf(sa[nf][1] - mn0);
            sa[nf][2] = __expf(sa[nf][2] - mn1);
            sa[nf][3] = __expf(sa[nf][3] - mn1);
            sum0 += sa[nf][0] + sa[nf][1];
            sum1 += sa[nf][2] + sa[nf][3];
        }
        sum0 += __shfl_xor_sync(0xffffffffu, sum0, 1);
        sum0 += __shfl_xor_sync(0xffffffffu, sum0, 2);
        sum1 += __shfl_xor_sync(0xffffffffu, sum1, 1);
        sum1 += __shfl_xor_sync(0xffffffffu, sum1, 2);
        lI0 = lI0 * c0 + sum0; mI0 = mn0;
        lI1 = lI1 * c1 + sum1; mI1 = mn1;
#pragma unroll
        for (int nf = 0; nf < 8; nf++) {
            oacc[nf][0] *= c0; oacc[nf][1] *= c0;
            oacc[nf][2] *= c1; oacc[nf][3] *= c1;
        }

        // round P (unbiased tf32) and stage to smem
        {
            int m0 = warp_m + lm;
#pragma unroll
            for (int nf = 0; nf < 8; nf++) {
                int cc = nf * 8 + 2 * lk;
                *(float2*)(Ps + m0 * FLD + cc) =
                    make_float2(round_tf32(sa[nf][0]), round_tf32(sa[nf][1]));
                *(float2*)(Ps + (m0 + 8) * FLD + cc) =
                    make_float2(round_tf32(sa[nf][2]), round_tf32(sa[nf][3]));
            }
        }
        __syncthreads();   // P + V visible

        // O += P @ V   (A = Ps[m][kv], B = Vs[d][kv])
#pragma unroll
        for (int ks = 0; ks < 8; ks++) {
            int m0 = warp_m + lm, k0 = ks * 8;
            uint32_t pa0 = __float_as_uint(Ps[m0 * FLD + k0 + lk]);
            uint32_t pa1 = __float_as_uint(Ps[(m0 + 8) * FLD + k0 + lk]);
            uint32_t pa2 = __float_as_uint(Ps[m0 * FLD + k0 + lk + 4]);
            uint32_t pa3 = __float_as_uint(Ps[(m0 + 8) * FLD + k0 + lk + 4]);
#pragma unroll
            for (int nf = 0; nf < 8; nf++) {
                int n = nf * 8 + lm;
                uint32_t b0 = __float_as_uint(Vs[n * FLD + k0 + lk]);
                uint32_t b1 = __float_as_uint(Vs[n * FLD + k0 + lk + 4]);
                mma_tf32(oacc[nf], pa0, pa1, pa2, pa3, b0, b1);
            }
        }
    }

    // epilogue: normalize, tf32-round (out-proj input), write [B*T, C]
    const float inv0 = 1.f / lI0, inv1 = 1.f / lI1;
    const int m0 = q0 + warp_m + lm;
    float* ob0 = out + (size_t)(b * T_ + m0) * C_ + h * D_;
    float* ob1 = out + (size_t)(b * T_ + m0 + 8) * C_ + h * D_;
#pragma unroll
    for (int nf = 0; nf < 8; nf++) {
        int cc = nf * 8 + 2 * lk;
        *(float2*)(ob0 + cc) = make_float2(round_tf32(oacc[nf][0] * inv0),
                                           round_tf32(oacc[nf][1] * inv0));
        *(float2*)(ob1 + cc) = make_float2(round_tf32(oacc[nf][2] * inv1),
                                           round_tf32(oacc[nf][3] * inv1));
    }
}

// ---------------------------------------------------------------------------
extern "C" void kernel_launch(void* const* d_in, const int* in_sizes, int n_in,
                              void* d_out, int out_size)
{
    const float* x     = (const float*)d_in[0];
    const float* w_qkv = (const float*)d_in[1];
    const float* w_out = (const float*)d_in[2];
    const float* b_out = (const float*)d_in[3];
    float* out = (float*)d_out;

    float *qkv_p, *attn_p, *xr_p, *wqkvr_p, *woutr_p;
    cudaGetSymbolAddress((void**)&qkv_p, g_qkv);
    cudaGetSymbolAddress((void**)&attn_p, g_attn);
    cudaGetSymbolAddress((void**)&xr_p, g_xr);
    cudaGetSymbolAddress((void**)&wqkvr_p, g_wqkvr);
    cudaGetSymbolAddress((void**)&woutr_p, g_woutr);

    const int M = B_ * T_;

    // 0) tf32-round GEMM inputs
    {
        int n4x = (M * C_) / 4;
        round_tf32_kernel<<<(n4x + 255) / 256, 256>>>((const float4*)x, (float4*)xr_p, n4x);
        int n4w = (3 * C_ * C_) / 4;
        round_tf32_kernel<<<(n4w + 255) / 256, 256>>>((const float4*)w_qkv, (float4*)wqkvr_p, n4w);
        int n4o = (C_ * C_) / 4;
        round_tf32_kernel<<<(n4o + 255) / 256, 256>>>((const float4*)w_out, (float4*)woutr_p, n4o);
    }

    cudaFuncSetAttribute(gemm_mma_tf32, cudaFuncAttributeMaxDynamicSharedMemorySize, G_SMEM);
    cudaFuncSetAttribute(flash_mma_kernel, cudaFuncAttributeMaxDynamicSharedMemorySize, FSMEM_BYTES);

    // 1) qkv = x @ w_qkv^T  [8192, 3072], tf32-rounded output
    {
        dim3 grid((3 * C_) / G_BN, M / G_BM);
        gemm_mma_tf32<<<grid, 256, G_SMEM>>>(xr_p, wqkvr_p, nullptr, qkv_p, 3 * C_, C_, 1);
    }

    // 2) flash attention (mma.sync tf32) -> g_attn [8192, 1024]
    {
        dim3 grid(T_ / FBM, B_ * H_);
        flash_mma_kernel<<<grid, 256, FSMEM_BYTES>>>(qkv_p, attn_p);
    }

    // 3) out = g_attn @ w_out^T + b_out  [8192, 1024]
    {
        dim3 grid(C_ / G_BN, M / G_BM);
        gemm_mma_tf32<<<grid, 256, G_SMEM>>>(attn_p, woutr_p, b_out, out, C_, C_, 0);
    }
}

// round 9
// speedup vs baseline: 6.3512x; 1.8069x over previous
#include <cuda_runtime.h>
#include <cuda_fp16.h>
#include <cstdint>
#include <math.h>

#define B_ 4
#define T_ 2048
#define C_ 1024
#define H_ 16
#define D_ 64

// Scratch (__device__ globals; allocation-free rule)
__device__ __half g_qkvh[(size_t)B_ * T_ * 3 * C_];   // [B*T, 3C] fp16
__device__ __half g_attnh[(size_t)B_ * T_ * C_];      // [B*T, C] fp16
__device__ __half g_xh[(size_t)B_ * T_ * C_];         // fp16 x
__device__ __half g_wqkvh[(size_t)3 * C_ * C_];       // fp16 w_qkv
__device__ __half g_wouth[(size_t)C_ * C_];           // fp16 w_out

// ---------------------------------------------------------------------------
__device__ __forceinline__ uint32_t smem_u32(const void* p) {
    uint32_t a;
    asm("{ .reg .u64 t; cvta.to.shared.u64 t, %1; cvt.u32.u64 %0, t; }" : "=r"(a) : "l"(p));
    return a;
}

__device__ __forceinline__ void cp_async16(uint32_t s, const void* g) {
    asm volatile("cp.async.cg.shared.global [%0], [%1], 16;" :: "r"(s), "l"(g));
}

__device__ __forceinline__ void mma_f16(float c[4], uint32_t a0, uint32_t a1,
                                        uint32_t a2, uint32_t a3,
                                        uint32_t b0, uint32_t b1)
{
    asm volatile(
        "mma.sync.aligned.m16n8k16.row.col.f32.f16.f16.f32 "
        "{%0,%1,%2,%3}, {%4,%5,%6,%7}, {%8,%9}, {%0,%1,%2,%3};"
        : "+f"(c[0]), "+f"(c[1]), "+f"(c[2]), "+f"(c[3])
        : "r"(a0), "r"(a1), "r"(a2), "r"(a3), "r"(b0), "r"(b1));
}

__device__ __forceinline__ uint32_t pack_h2(float lo, float hi) {
    __half2 h = __floats2half2_rn(lo, hi);
    return *(uint32_t*)&h;
}

// ---------------------------------------------------------------------------
// fp32 -> fp16 (RTN) convert pre-pass: 8 elems/thread
// ---------------------------------------------------------------------------
__global__ __launch_bounds__(256) void f32_to_f16_kernel(
    const float4* __restrict__ in, uint4* __restrict__ out, int n8)
{
    int i = blockIdx.x * blockDim.x + threadIdx.x;
    if (i >= n8) return;
    float4 a = in[2 * i], b = in[2 * i + 1];
    uint4 o;
    o.x = pack_h2(a.x, a.y); o.y = pack_h2(a.z, a.w);
    o.z = pack_h2(b.x, b.y); o.w = pack_h2(b.z, b.w);
    out[i] = o;
}

// ---------------------------------------------------------------------------
// fp16 mma.sync GEMM:  C[m,n] = sum_k A[m,k]*Bw[n,k] (+bias[n])
// A:[M,K], Bw:[N,K] row-major fp16. BM=BN=128, BK=64 halves, 3-stage
// cp.async, 8 warps, warp tile 64x32 via m16n8k16.
// out_half: write fp16 (RN); else fp32 + bias.
// ---------------------------------------------------------------------------
#define G_BM 128
#define G_BN 128
#define G_BK 64
#define G_ST 3
#define G_LDH 72                                   // halves; conflict-free frags
#define STAGE_H ((G_BM + G_BN) * G_LDH)            // 18432 halves = 36864 B
#define G_SMEM (G_ST * STAGE_H * 2)                // 110592 B

__global__ __launch_bounds__(256, 1) void gemm_mma_f16(
    const __half* __restrict__ A, const __half* __restrict__ Bw,
    const float* __restrict__ bias, float* __restrict__ Cf,
    __half* __restrict__ Ch, int N, int K)
{
    extern __shared__ __half smh[];
    const int tid = threadIdx.x;
    const int lane = tid & 31, wid = tid >> 5;
    const int warp_m = (wid >> 2) * 64;
    const int warp_n = (wid & 3) * 32;
    const int bm = blockIdx.y * G_BM;
    const int bn = blockIdx.x * G_BN;
    const int nk = K / G_BK;

    const int lm = lane >> 2;
    const int lk = lane & 3;

    float c[4][4][4];
#pragma unroll
    for (int mf = 0; mf < 4; mf++)
#pragma unroll
        for (int nf = 0; nf < 4; nf++)
#pragma unroll
            for (int r = 0; r < 4; r++) c[mf][nf][r] = 0.f;

    const __half* Ab = A + (size_t)bm * K;
    const __half* Bb = Bw + (size_t)bn * K;
    uint32_t smbase = smem_u32(smh);

    // 256 rows (A:128 + B:128), 64 halves/row = 8 x 16B segs; 2048 total
    auto issue_stage = [&](int chunk, int s) {
        uint32_t st = smbase + (uint32_t)(s * STAGE_H) * 2;
        const __half* Ag = Ab + (size_t)chunk * G_BK;
        const __half* Bg = Bb + (size_t)chunk * G_BK;
#pragma unroll
        for (int it = 0; it < 8; it++) {
            int e = tid + it * 256;
            int row = e >> 3, seg = e & 7;
            const __half* src = (row < 128)
                ? Ag + (size_t)row * K + seg * 8
                : Bg + (size_t)(row - 128) * K + seg * 8;
            cp_async16(st + (uint32_t)(row * G_LDH + seg * 8) * 2, src);
        }
    };

#pragma unroll
    for (int s = 0; s < G_ST - 1; s++) {
        issue_stage(s, s);
        asm volatile("cp.async.commit_group;" ::: "memory");
    }

    for (int i = 0; i < nk; i++) {
        if (i + G_ST - 1 < nk) issue_stage(i + G_ST - 1, (i + G_ST - 1) % G_ST);
        asm volatile("cp.async.commit_group;" ::: "memory");
        asm volatile("cp.async.wait_group 2;" ::: "memory");
        __syncthreads();

        const __half* As = smh + (i % G_ST) * STAGE_H;
        const __half* Bs = As + G_BM * G_LDH;

#pragma unroll
        for (int ks = 0; ks < 4; ks++) {                 // 4 x k16
            const int k0 = ks * 16;
            uint32_t a[4][4], b[4][2];
#pragma unroll
            for (int mf = 0; mf < 4; mf++) {
                int m = warp_m + mf * 16 + lm;
                a[mf][0] = *(const uint32_t*)(As + m * G_LDH + k0 + 2 * lk);
                a[mf][1] = *(const uint32_t*)(As + (m + 8) * G_LDH + k0 + 2 * lk);
                a[mf][2] = *(const uint32_t*)(As + m * G_LDH + k0 + 8 + 2 * lk);
                a[mf][3] = *(const uint32_t*)(As + (m + 8) * G_LDH + k0 + 8 + 2 * lk);
            }
#pragma unroll
            for (int nf = 0; nf < 4; nf++) {
                int n = warp_n + nf * 8 + lm;
                b[nf][0] = *(const uint32_t*)(Bs + n * G_LDH + k0 + 2 * lk);
                b[nf][1] = *(const uint32_t*)(Bs + n * G_LDH + k0 + 8 + 2 * lk);
            }
#pragma unroll
            for (int mf = 0; mf < 4; mf++)
#pragma unroll
                for (int nf = 0; nf < 4; nf++)
                    mma_f16(c[mf][nf], a[mf][0], a[mf][1], a[mf][2], a[mf][3],
                            b[nf][0], b[nf][1]);
        }
        __syncthreads();
    }

#pragma unroll
    for (int mf = 0; mf < 4; mf++) {
        int m = bm + warp_m + mf * 16 + lm;
#pragma unroll
        for (int nf = 0; nf < 4; nf++) {
            int n = bn + warp_n + nf * 8 + 2 * lk;
            if (Ch) {
                *(uint32_t*)(Ch + (size_t)m * N + n) = pack_h2(c[mf][nf][0], c[mf][nf][1]);
                *(uint32_t*)(Ch + (size_t)(m + 8) * N + n) = pack_h2(c[mf][nf][2], c[mf][nf][3]);
            } else {
                float bx = bias ? bias[n] : 0.f, by = bias ? bias[n + 1] : 0.f;
                *(float2*)(Cf + (size_t)m * N + n) =
                    make_float2(c[mf][nf][0] + bx, c[mf][nf][1] + by);
                *(float2*)(Cf + (size_t)(m + 8) * N + n) =
                    make_float2(c[mf][nf][2] + bx, c[mf][nf][3] + by);
            }
        }
    }
}

// ---------------------------------------------------------------------------
// Flash attention, fp16 mma.sync. BM=128 q-rows/CTA, BN=64 kv/iter, 8 warps.
// Q frags in regs; K double-buffered cp.async; V transposed in smem; P via smem.
// ---------------------------------------------------------------------------
#define FBM 128
#define FBN 64
#define FLDH 72
#define KSTG (64 * FLDH)               // halves
#define VOFF (2 * KSTG)
#define POFF (VOFF + 64 * FLDH)
#define FSM_H (POFF + 128 * FLDH)      // 23040 halves
#define FSM_BYTES (FSM_H * 2)          // 46080 B

__global__ __launch_bounds__(256, 1) void flash_mma_f16(
    const __half* __restrict__ qkv, __half* __restrict__ out)
{
    extern __shared__ __half smh[];
    __half* Vs = smh + VOFF;
    __half* Ps = smh + POFF;

    const int tid = threadIdx.x, lane = tid & 31, wid = tid >> 5;
    const int lm = lane >> 2, lk = lane & 3;
    const int warp_m = wid * 16;
    const int qtile = gridDim.x - 1 - blockIdx.x;    // heavy tiles first
    const int q0 = qtile * FBM;
    const int bh = blockIdx.y;
    const int b = bh >> 4, h = bh & 15;
    const size_t rs = 3 * C_;

    const __half* qptr = qkv + (size_t)(b * T_ + q0) * rs + h * D_;
    const __half* kptr0 = qkv + (size_t)(b * T_) * rs + C_ + h * D_;
    const __half* vptr0 = kptr0 + C_;

    uint32_t smb = smem_u32(smh);
    const int nit = q0 / FBN + 2;

    // K tile: 64 rows x 64 halves = 8 x 16B segs/row
    auto load_k = [&](int it, int s) {
        const __half* kg = kptr0 + (size_t)(it * FBN) * rs;
        uint32_t dst = smb + (uint32_t)(s * KSTG) * 2;
        int seg = tid & 7, r0 = tid >> 3;
#pragma unroll
        for (int i = 0; i < 2; i++) {
            int r = r0 + i * 32;
            cp_async16(dst + (uint32_t)(r * FLDH + seg * 8) * 2,
                       kg + (size_t)r * rs + seg * 8);
        }
    };

    load_k(0, 0);
    asm volatile("cp.async.commit_group;" ::: "memory");

    // Stage Q (128 x 64 halves) into Ps, coalesced 16B
    {
        int seg = tid & 7, r0 = tid >> 3;
#pragma unroll
        for (int i = 0; i < 4; i++) {
            int r = r0 + i * 32;
            *(uint4*)(Ps + r * FLDH + seg * 8) =
                *(const uint4*)(qptr + (size_t)r * rs + seg * 8);
        }
    }
    __syncthreads();
    uint32_t qf[4][4];
#pragma unroll
    for (int ks = 0; ks < 4; ks++) {
        int m0 = warp_m + lm, k0 = ks * 16;
        qf[ks][0] = *(const uint32_t*)(Ps + m0 * FLDH + k0 + 2 * lk);
        qf[ks][1] = *(const uint32_t*)(Ps + (m0 + 8) * FLDH + k0 + 2 * lk);
        qf[ks][2] = *(const uint32_t*)(Ps + m0 * FLDH + k0 + 8 + 2 * lk);
        qf[ks][3] = *(const uint32_t*)(Ps + (m0 + 8) * FLDH + k0 + 8 + 2 * lk);
    }

    float mI0 = -INFINITY, mI1 = -INFINITY, lI0 = 0.f, lI1 = 0.f;
    float oacc[8][4];
#pragma unroll
    for (int nf = 0; nf < 8; nf++)
#pragma unroll
        for (int r = 0; r < 4; r++) oacc[nf][r] = 0.f;

    const float scl = 0.125f;

    for (int it = 0; it < nit; it++) {
        const int s = it & 1;
        if (it + 1 < nit) {
            load_k(it + 1, s ^ 1);
            asm volatile("cp.async.commit_group;" ::: "memory");
            asm volatile("cp.async.wait_group 1;" ::: "memory");
        } else {
            asm volatile("cp.async.wait_group 0;" ::: "memory");
        }
        __syncthreads();

        // V tile -> regs (overlap with S-mma)
        const __half* vg = vptr0 + (size_t)(it * FBN) * rs;
        const int kv = tid & 63, db = tid >> 6;
        __half vtmp[16];
        *(uint4*)(vtmp) = *(const uint4*)(vg + (size_t)kv * rs + db * 16);
        *(uint4*)(vtmp + 8) = *(const uint4*)(vg + (size_t)kv * rs + db * 16 + 8);

        // S = Q K^T
        float sa[8][4];
#pragma unroll
        for (int nf = 0; nf < 8; nf++)
#pragma unroll
            for (int r = 0; r < 4; r++) sa[nf][r] = 0.f;

        const __half* Kst = smh + s * KSTG;
#pragma unroll
        for (int ks = 0; ks < 4; ks++) {
            const int k0 = ks * 16;
            uint32_t bf[8][2];
#pragma unroll
            for (int nf = 0; nf < 8; nf++) {
                int n = nf * 8 + lm;
                bf[nf][0] = *(const uint32_t*)(Kst + n * FLDH + k0 + 2 * lk);
                bf[nf][1] = *(const uint32_t*)(Kst + n * FLDH + k0 + 8 + 2 * lk);
            }
#pragma unroll
            for (int nf = 0; nf < 8; nf++)
                mma_f16(sa[nf], qf[ks][0], qf[ks][1], qf[ks][2], qf[ks][3],
                        bf[nf][0], bf[nf][1]);
        }

        // store V transposed: Vs[d][kv]
#pragma unroll
        for (int j = 0; j < 16; j++)
            Vs[(db * 16 + j) * FLDH + kv] = vtmp[j];

        // scale + causal mask
        const int k0g = it * FBN;
        if (it >= nit - 2) {
#pragma unroll
            for (int nf = 0; nf < 8; nf++)
#pragma unroll
                for (int r = 0; r < 4; r++) {
                    int i_loc = warp_m + lm + ((r >= 2) ? 8 : 0);
                    int j_loc = nf * 8 + 2 * lk + (r & 1);
                    float v = sa[nf][r] * scl;
                    sa[nf][r] = (k0g + j_loc > q0 + i_loc) ? -INFINITY : v;
                }
        } else {
#pragma unroll
            for (int nf = 0; nf < 8; nf++)
#pragma unroll
                for (int r = 0; r < 4; r++) sa[nf][r] *= scl;
        }

        // online softmax
        float mx0 = -INFINITY, mx1 = -INFINITY;
#pragma unroll
        for (int nf = 0; nf < 8; nf++) {
            mx0 = fmaxf(mx0, fmaxf(sa[nf][0], sa[nf][1]));
            mx1 = fmaxf(mx1, fmaxf(sa[nf][2], sa[nf][3]));
        }
        mx0 = fmaxf(mx0, __shfl_xor_sync(0xffffffffu, mx0, 1));
        mx0 = fmaxf(mx0, __shfl_xor_sync(0xffffffffu, mx0, 2));
        mx1 = fmaxf(mx1, __shfl_xor_sync(0xffffffffu, mx1, 1));
        mx1 = fmaxf(mx1, __shfl_xor_sync(0xffffffffu, mx1, 2));

        float mn0 = fmaxf(mI0, mx0), mn1 = fmaxf(mI1, mx1);
        float c0 = __expf(mI0 - mn0), c1 = __expf(mI1 - mn1);
        float sum0 = 0.f, sum1 = 0.f;
#pragma unroll
        for (int nf = 0; nf < 8; nf++) {
            sa[nf][0] = __expf(sa[nf][0] - mn0);
            sa[nf][1] = __expf(sa[nf][1] - mn0);
            sa[nf][2] = __expf(sa[nf][2] - mn1);
            sa[nf][3] = __expf(sa[nf][3] - mn1);
            sum0 += sa[nf][0] + sa[nf][1];
            sum1 += sa[nf][2] + sa[nf][3];
        }
        sum0 += __shfl_xor_sync(0xffffffffu, sum0, 1);
        sum0 += __shfl_xor_sync(0xffffffffu, sum0, 2);
        sum1 += __shfl_xor_sync(0xffffffffu, sum1, 1);
        sum1 += __shfl_xor_sync(0xffffffffu, sum1, 2);
        lI0 = lI0 * c0 + sum0; mI0 = mn0;
        lI1 = lI1 * c1 + sum1; mI1 = mn1;
#pragma unroll
        for (int nf = 0; nf < 8; nf++) {
            oacc[nf][0] *= c0; oacc[nf][1] *= c0;
            oacc[nf][2] *= c1; oacc[nf][3] *= c1;
        }

        // P -> fp16 (RN) staged to smem
        {
            int m0 = warp_m + lm;
#pragma unroll
            for (int nf = 0; nf < 8; nf++) {
                int cc = nf * 8 + 2 * lk;
                *(uint32_t*)(Ps + m0 * FLDH + cc) = pack_h2(sa[nf][0], sa[nf][1]);
                *(uint32_t*)(Ps + (m0 + 8) * FLDH + cc) = pack_h2(sa[nf][2], sa[nf][3]);
            }
        }
        __syncthreads();   // P + V visible

        // O += P @ V   (A = Ps[m][kv], B = Vs[d][kv])
#pragma unroll
        for (int ks = 0; ks < 4; ks++) {
            int m0 = warp_m + lm, k0 = ks * 16;
            uint32_t pa0 = *(const uint32_t*)(Ps + m0 * FLDH + k0 + 2 * lk);
            uint32_t pa1 = *(const uint32_t*)(Ps + (m0 + 8) * FLDH + k0 + 2 * lk);
            uint32_t pa2 = *(const uint32_t*)(Ps + m0 * FLDH + k0 + 8 + 2 * lk);
            uint32_t pa3 = *(const uint32_t*)(Ps + (m0 + 8) * FLDH + k0 + 8 + 2 * lk);
#pragma unroll
            for (int nf = 0; nf < 8; nf++) {
                int n = nf * 8 + lm;
                uint32_t b0 = *(const uint32_t*)(Vs + n * FLDH + k0 + 2 * lk);
                uint32_t b1 = *(const uint32_t*)(Vs + n * FLDH + k0 + 8 + 2 * lk);
                mma_f16(oacc[nf], pa0, pa1, pa2, pa3, b0, b1);
            }
        }
    }

    // epilogue: normalize, fp16 (RN), write [B*T, C]
    const float inv0 = 1.f / lI0, inv1 = 1.f / lI1;
    const int m0 = q0 + warp_m + lm;
    __half* ob0 = out + (size_t)(b * T_ + m0) * C_ + h * D_;
    __half* ob1 = out + (size_t)(b * T_ + m0 + 8) * C_ + h * D_;
#pragma unroll
    for (int nf = 0; nf < 8; nf++) {
        int cc = nf * 8 + 2 * lk;
        *(uint32_t*)(ob0 + cc) = pack_h2(oacc[nf][0] * inv0, oacc[nf][1] * inv0);
        *(uint32_t*)(ob1 + cc) = pack_h2(oacc[nf][2] * inv1, oacc[nf][3] * inv1);
    }
}

// ---------------------------------------------------------------------------
extern "C" void kernel_launch(void* const* d_in, const int* in_sizes, int n_in,
                              void* d_out, int out_size)
{
    const float* x     = (const float*)d_in[0];
    const float* w_qkv = (const float*)d_in[1];
    const float* w_out = (const float*)d_in[2];
    const float* b_out = (const float*)d_in[3];
    float* out = (float*)d_out;

    __half *qkv_p, *attn_p, *xh_p, *wqkvh_p, *wouth_p;
    cudaGetSymbolAddress((void**)&qkv_p, g_qkvh);
    cudaGetSymbolAddress((void**)&attn_p, g_attnh);
    cudaGetSymbolAddress((void**)&xh_p, g_xh);
    cudaGetSymbolAddress((void**)&wqkvh_p, g_wqkvh);
    cudaGetSymbolAddress((void**)&wouth_p, g_wouth);

    const int M = B_ * T_;

    // 0) fp32 -> fp16 (RTN) conversions
    {
        int n8x = (M * C_) / 8;
        f32_to_f16_kernel<<<(n8x + 255) / 256, 256>>>((const float4*)x, (uint4*)xh_p, n8x);
        int n8w = (3 * C_ * C_) / 8;
        f32_to_f16_kernel<<<(n8w + 255) / 256, 256>>>((const float4*)w_qkv, (uint4*)wqkvh_p, n8w);
        int n8o = (C_ * C_) / 8;
        f32_to_f16_kernel<<<(n8o + 255) / 256, 256>>>((const float4*)w_out, (uint4*)wouth_p, n8o);
    }

    cudaFuncSetAttribute(gemm_mma_f16, cudaFuncAttributeMaxDynamicSharedMemorySize, G_SMEM);
    cudaFuncSetAttribute(flash_mma_f16, cudaFuncAttributeMaxDynamicSharedMemorySize, FSM_BYTES);

    // 1) qkv = x @ w_qkv^T  [8192, 3072] -> fp16
    {
        dim3 grid((3 * C_) / G_BN, M / G_BM);
        gemm_mma_f16<<<grid, 256, G_SMEM>>>(xh_p, wqkvh_p, nullptr, nullptr, qkv_p, 3 * C_, C_);
    }

    // 2) flash attention (fp16 mma) -> g_attnh
    {
        dim3 grid(T_ / FBM, B_ * H_);
        flash_mma_f16<<<grid, 256, FSM_BYTES>>>(qkv_p, attn_p);
    }

    // 3) out = g_attn @ w_out^T + b_out  [8192, 1024] -> fp32
    {
        dim3 grid(C_ / G_BN, M / G_BM);
        gemm_mma_f16<<<grid, 256, G_SMEM>>>(attn_p, wouth_p, b_out, out, nullptr, C_, C_);
    }
}

// round 10
// speedup vs baseline: 7.7916x; 1.2268x over previous
#include <cuda_runtime.h>
#include <cuda_fp16.h>
#include <cstdint>
#include <math.h>

#define B_ 4
#define T_ 2048
#define C_ 1024
#define H_ 16
#define D_ 64

// Scratch (__device__ globals; allocation-free rule)
__device__ __half g_qkvh[(size_t)B_ * T_ * 3 * C_];   // [B*T, 3C] fp16
__device__ __half g_attnh[(size_t)B_ * T_ * C_];      // [B*T, C] fp16
__device__ __half g_xh[(size_t)B_ * T_ * C_];         // fp16 x
__device__ __half g_wqkvh[(size_t)3 * C_ * C_];       // fp16 w_qkv
__device__ __half g_wouth[(size_t)C_ * C_];           // fp16 w_out

// ---------------------------------------------------------------------------
__device__ __forceinline__ uint32_t smem_u32(const void* p) {
    uint32_t a;
    asm("{ .reg .u64 t; cvta.to.shared.u64 t, %1; cvt.u32.u64 %0, t; }" : "=r"(a) : "l"(p));
    return a;
}

__device__ __forceinline__ void cp_async16(uint32_t s, const void* g) {
    asm volatile("cp.async.cg.shared.global [%0], [%1], 16;" :: "r"(s), "l"(g));
}

__device__ __forceinline__ void mma_f16(float c[4], uint32_t a0, uint32_t a1,
                                        uint32_t a2, uint32_t a3,
                                        uint32_t b0, uint32_t b1)
{
    asm volatile(
        "mma.sync.aligned.m16n8k16.row.col.f32.f16.f16.f32 "
        "{%0,%1,%2,%3}, {%4,%5,%6,%7}, {%8,%9}, {%0,%1,%2,%3};"
        : "+f"(c[0]), "+f"(c[1]), "+f"(c[2]), "+f"(c[3])
        : "r"(a0), "r"(a1), "r"(a2), "r"(a3), "r"(b0), "r"(b1));
}

__device__ __forceinline__ void ldmx4(uint32_t& r0, uint32_t& r1, uint32_t& r2,
                                      uint32_t& r3, uint32_t a)
{
    asm volatile("ldmatrix.sync.aligned.m8n8.x4.shared.b16 {%0,%1,%2,%3}, [%4];"
                 : "=r"(r0), "=r"(r1), "=r"(r2), "=r"(r3) : "r"(a));
}

__device__ __forceinline__ void ldmx4t(uint32_t& r0, uint32_t& r1, uint32_t& r2,
                                       uint32_t& r3, uint32_t a)
{
    asm volatile("ldmatrix.sync.aligned.m8n8.x4.trans.shared.b16 {%0,%1,%2,%3}, [%4];"
                 : "=r"(r0), "=r"(r1), "=r"(r2), "=r"(r3) : "r"(a));
}

__device__ __forceinline__ uint32_t pack_h2(float lo, float hi) {
    __half2 h = __floats2half2_rn(lo, hi);
    return *(uint32_t*)&h;
}

// ---------------------------------------------------------------------------
// fp32 -> fp16 (RTN) convert pre-pass
// ---------------------------------------------------------------------------
__global__ __launch_bounds__(256) void f32_to_f16_kernel(
    const float4* __restrict__ in, uint4* __restrict__ out, int n8)
{
    int i = blockIdx.x * blockDim.x + threadIdx.x;
    if (i >= n8) return;
    float4 a = in[2 * i], b = in[2 * i + 1];
    uint4 o;
    o.x = pack_h2(a.x, a.y); o.y = pack_h2(a.z, a.w);
    o.z = pack_h2(b.x, b.y); o.w = pack_h2(b.z, b.w);
    out[i] = o;
}

// ---------------------------------------------------------------------------
// fp16 mma.sync GEMM, ldmatrix fragments, single-sync 3-stage pipeline,
// 2 CTAs/SM target. C[m,n] = sum_k A[m,k]*Bw[n,k] (+bias).
// ---------------------------------------------------------------------------
#define G_BM 128
#define G_BN 128
#define G_BK 64
#define G_ST 3
#define G_LDH 72
#define STAGE_H ((G_BM + G_BN) * G_LDH)            // 18432 halves
#define G_SMEM (G_ST * STAGE_H * 2)                // 110592 B

__global__ __launch_bounds__(256, 2) void gemm_mma_f16(
    const __half* __restrict__ A, const __half* __restrict__ Bw,
    const float* __restrict__ bias, float* __restrict__ Cf,
    __half* __restrict__ Ch, int N, int K)
{
    extern __shared__ __half smh[];
    const int tid = threadIdx.x;
    const int lane = tid & 31, wid = tid >> 5;
    const int warp_m = (wid >> 2) * 64;
    const int warp_n = (wid & 3) * 32;
    const int bm = blockIdx.y * G_BM;
    const int bn = blockIdx.x * G_BN;
    const int nk = K / G_BK;
    const int lm = lane >> 2, lk = lane & 3;
    const int g = lane >> 3, li = lane & 7;

    float c[4][4][4];
#pragma unroll
    for (int mf = 0; mf < 4; mf++)
#pragma unroll
        for (int nf = 0; nf < 4; nf++)
#pragma unroll
            for (int r = 0; r < 4; r++) c[mf][nf][r] = 0.f;

    const __half* Ab = A + (size_t)bm * K;
    const __half* Bb = Bw + (size_t)bn * K;
    uint32_t smbase = smem_u32(smh);

    // ldmatrix per-thread fragment base offsets (bytes)
    const uint32_t fa = (uint32_t)(((warp_m + ((g & 1) << 3) + li) * G_LDH + ((g >> 1) << 3)) * 2);
    const uint32_t fb = (uint32_t)(((128 + warp_n + ((g & 1) << 3) + li) * G_LDH + ((g >> 1) << 3)) * 2);

    auto issue_stage = [&](int chunk, int s) {
        uint32_t st = smbase + (uint32_t)(s * STAGE_H) * 2;
        const __half* Ag = Ab + (size_t)chunk * G_BK;
        const __half* Bg = Bb + (size_t)chunk * G_BK;
#pragma unroll
        for (int it = 0; it < 8; it++) {
            int e = tid + it * 256;
            int row = e >> 3, seg = e & 7;
            const __half* src = (row < 128)
                ? Ag + (size_t)row * K + seg * 8
                : Bg + (size_t)(row - 128) * K + seg * 8;
            cp_async16(st + (uint32_t)(row * G_LDH + seg * 8) * 2, src);
        }
    };

#pragma unroll
    for (int s = 0; s < G_ST - 1; s++) {
        issue_stage(s, s);
        asm volatile("cp.async.commit_group;" ::: "memory");
    }

    for (int i = 0; i < nk; i++) {
        asm volatile("cp.async.wait_group %0;" :: "n"(G_ST - 2) : "memory");
        __syncthreads();                    // stage i ready; stage (i-1)%ST free
        if (i + G_ST - 1 < nk) issue_stage(i + G_ST - 1, (i + G_ST - 1) % G_ST);
        asm volatile("cp.async.commit_group;" ::: "memory");

        const uint32_t st = smbase + (uint32_t)((i % G_ST) * STAGE_H) * 2;
#pragma unroll
        for (int ks = 0; ks < 4; ks++) {
            uint32_t a[4][4], b0[2], b1[2], b2[2], b3[2];
#pragma unroll
            for (int mf = 0; mf < 4; mf++)
                ldmx4(a[mf][0], a[mf][1], a[mf][2], a[mf][3],
                      st + fa + (uint32_t)((mf * 16 * G_LDH + ks * 16) * 2));
#pragma unroll
            for (int p = 0; p < 2; p++)
                ldmx4(b0[p], b1[p], b2[p], b3[p],
                      st + fb + (uint32_t)((p * 16 * G_LDH + ks * 16) * 2));
#pragma unroll
            for (int mf = 0; mf < 4; mf++)
#pragma unroll
                for (int p = 0; p < 2; p++) {
                    mma_f16(c[mf][2 * p], a[mf][0], a[mf][1], a[mf][2], a[mf][3],
                            b0[p], b2[p]);
                    mma_f16(c[mf][2 * p + 1], a[mf][0], a[mf][1], a[mf][2], a[mf][3],
                            b1[p], b3[p]);
                }
        }
    }

#pragma unroll
    for (int mf = 0; mf < 4; mf++) {
        int m = bm + warp_m + mf * 16 + lm;
#pragma unroll
        for (int nf = 0; nf < 4; nf++) {
            int n = bn + warp_n + nf * 8 + 2 * lk;
            if (Ch) {
                *(uint32_t*)(Ch + (size_t)m * N + n) = pack_h2(c[mf][nf][0], c[mf][nf][1]);
                *(uint32_t*)(Ch + (size_t)(m + 8) * N + n) = pack_h2(c[mf][nf][2], c[mf][nf][3]);
            } else {
                float bx = bias ? bias[n] : 0.f, by = bias ? bias[n + 1] : 0.f;
                *(float2*)(Cf + (size_t)m * N + n) =
                    make_float2(c[mf][nf][0] + bx, c[mf][nf][1] + by);
                *(float2*)(Cf + (size_t)(m + 8) * N + n) =
                    make_float2(c[mf][nf][2] + bx, c[mf][nf][3] + by);
            }
        }
    }
}

// ---------------------------------------------------------------------------
// Flash attention, fp16 mma + ldmatrix. BM=128, BN=64, 8 warps.
// Q frags in regs; K,V 3-stage cp.async; V via ldmatrix.trans (no transpose
// pass); P kept in registers (S-accum fragment == PV A-fragment layout).
// ONE __syncthreads per kv iteration.
// ---------------------------------------------------------------------------
#define FBM 128
#define FBN 64
#define FLDH 72
#define KSTG (64 * FLDH)                       // 4608 halves per tile stage
#define QOFF (6 * KSTG)                        // after 3 K + 3 V stages
#define FSM_H (QOFF + 128 * FLDH)              // 36864 halves
#define FSM_BYTES (FSM_H * 2)                  // 73728 B

__global__ __launch_bounds__(256, 2) void flash_mma_f16(
    const __half* __restrict__ qkv, __half* __restrict__ out)
{
    extern __shared__ __half smh[];
    const int tid = threadIdx.x, lane = tid & 31, wid = tid >> 5;
    const int lm = lane >> 2, lk = lane & 3;
    const int g = lane >> 3, li = lane & 7;
    const int warp_m = wid * 16;
    const int qtile = gridDim.x - 1 - blockIdx.x;    // heavy tiles first
    const int q0 = qtile * FBM;
    const int bh = blockIdx.y;
    const int b = bh >> 4, h = bh & 15;
    const size_t rs = 3 * C_;

    const __half* qptr = qkv + (size_t)(b * T_ + q0) * rs + h * D_;
    const __half* kptr0 = qkv + (size_t)(b * T_) * rs + C_ + h * D_;
    const __half* vptr0 = kptr0 + C_;

    uint32_t smb = smem_u32(smh);
    const int nit = q0 / FBN + 2;

    // fragment base offsets
    const uint32_t fkb = (uint32_t)(((((g & 1) << 3) + li) * FLDH + ((g >> 1) << 3)) * 2);
    const uint32_t fvb = (uint32_t)(((((g >> 1) << 3) + li) * FLDH + ((g & 1) << 3)) * 2);
    const uint32_t fqb = (uint32_t)(QOFF * 2) +
        (uint32_t)(((warp_m + ((g & 1) << 3) + li) * FLDH + ((g >> 1) << 3)) * 2);

    auto load_kv = [&](int it, int s) {
        const __half* kg = kptr0 + (size_t)(it * FBN) * rs;
        const __half* vg = vptr0 + (size_t)(it * FBN) * rs;
        uint32_t kd = smb + (uint32_t)(s * KSTG) * 2;
        uint32_t vd = smb + (uint32_t)((3 + s) * KSTG) * 2;
        int seg = tid & 7, r0 = tid >> 3;
#pragma unroll
        for (int i = 0; i < 2; i++) {
            int r = r0 + i * 32;
            cp_async16(kd + (uint32_t)(r * FLDH + seg * 8) * 2, kg + (size_t)r * rs + seg * 8);
            cp_async16(vd + (uint32_t)(r * FLDH + seg * 8) * 2, vg + (size_t)r * rs + seg * 8);
        }
    };

    load_kv(0, 0);
    asm volatile("cp.async.commit_group;" ::: "memory");
    load_kv(1, 1);
    asm volatile("cp.async.commit_group;" ::: "memory");

    // Stage Q (128 x 64 halves), coalesced 16B stores
    {
        int seg = tid & 7, r0 = tid >> 3;
#pragma unroll
        for (int i = 0; i < 4; i++) {
            int r = r0 + i * 32;
            *(uint4*)(smh + QOFF + r * FLDH + seg * 8) =
                *(const uint4*)(qptr + (size_t)r * rs + seg * 8);
        }
    }
    __syncthreads();
    uint32_t qf[4][4];
#pragma unroll
    for (int ks = 0; ks < 4; ks++)
        ldmx4(qf[ks][0], qf[ks][1], qf[ks][2], qf[ks][3],
              smb + fqb + (uint32_t)(ks * 16 * 2));

    float mI0 = -INFINITY, mI1 = -INFINITY, lI0 = 0.f, lI1 = 0.f;
    float oacc[8][4];
#pragma unroll
    for (int nf = 0; nf < 8; nf++)
#pragma unroll
        for (int r = 0; r < 4; r++) oacc[nf][r] = 0.f;

    const float scl = 0.125f;

    for (int it = 0; it < nit; it++) {
        const int s = it % 3;
        asm volatile("cp.async.wait_group 1;" ::: "memory");   // chunk it done
        __syncthreads();                                       // + stage (it-1)%3 free
        if (it + 2 < nit) load_kv(it + 2, (it + 2) % 3);
        asm volatile("cp.async.commit_group;" ::: "memory");

        // S = Q K^T
        float sa[8][4];
#pragma unroll
        for (int nf = 0; nf < 8; nf++)
#pragma unroll
            for (int r = 0; r < 4; r++) sa[nf][r] = 0.f;

        const uint32_t ksA = smb + (uint32_t)(s * KSTG) * 2;
#pragma unroll
        for (int ks = 0; ks < 4; ks++) {
#pragma unroll
            for (int p = 0; p < 4; p++) {
                uint32_t k0r, k1r, k2r, k3r;
                ldmx4(k0r, k1r, k2r, k3r,
                      ksA + fkb + (uint32_t)((p * 16 * FLDH + ks * 16) * 2));
                mma_f16(sa[2 * p], qf[ks][0], qf[ks][1], qf[ks][2], qf[ks][3], k0r, k2r);
                mma_f16(sa[2 * p + 1], qf[ks][0], qf[ks][1], qf[ks][2], qf[ks][3], k1r, k3r);
            }
        }

        // scale + causal mask (only last two tiles)
        const int k0g = it * FBN;
        if (it >= nit - 2) {
#pragma unroll
            for (int nf = 0; nf < 8; nf++)
#pragma unroll
                for (int r = 0; r < 4; r++) {
                    int i_loc = warp_m + lm + ((r >= 2) ? 8 : 0);
                    int j_loc = nf * 8 + 2 * lk + (r & 1);
                    float v = sa[nf][r] * scl;
                    sa[nf][r] = (k0g + j_loc > q0 + i_loc) ? -INFINITY : v;
                }
        } else {
#pragma unroll
            for (int nf = 0; nf < 8; nf++)
#pragma unroll
                for (int r = 0; r < 4; r++) sa[nf][r] *= scl;
        }

        // online softmax
        float mx0 = -INFINITY, mx1 = -INFINITY;
#pragma unroll
        for (int nf = 0; nf < 8; nf++) {
            mx0 = fmaxf(mx0, fmaxf(sa[nf][0], sa[nf][1]));
            mx1 = fmaxf(mx1, fmaxf(sa[nf][2], sa[nf][3]));
        }
        mx0 = fmaxf(mx0, __shfl_xor_sync(0xffffffffu, mx0, 1));
        mx0 = fmaxf(mx0, __shfl_xor_sync(0xffffffffu, mx0, 2));
        mx1 = fmaxf(mx1, __shfl_xor_sync(0xffffffffu, mx1, 1));
        mx1 = fmaxf(mx1, __shfl_xor_sync(0xffffffffu, mx1, 2));

        float mn0 = fmaxf(mI0, mx0), mn1 = fmaxf(mI1, mx1);
        float c0 = __expf(mI0 - mn0), c1 = __expf(mI1 - mn1);
        float sum0 = 0.f, sum1 = 0.f;
#pragma unroll
        for (int nf = 0; nf < 8; nf++) {
            sa[nf][0] = __expf(sa[nf][0] - mn0);
            sa[nf][1] = __expf(sa[nf][1] - mn0);
            sa[nf][2] = __expf(sa[nf][2] - mn1);
            sa[nf][3] = __expf(sa[nf][3] - mn1);
            sum0 += sa[nf][0] + sa[nf][1];
            sum1 += sa[nf][2] + sa[nf][3];
        }
        sum0 += __shfl_xor_sync(0xffffffffu, sum0, 1);
        sum0 += __shfl_xor_sync(0xffffffffu, sum0, 2);
        sum1 += __shfl_xor_sync(0xffffffffu, sum1, 1);
        sum1 += __shfl_xor_sync(0xffffffffu, sum1, 2);
        lI0 = lI0 * c0 + sum0; mI0 = mn0;
        lI1 = lI1 * c1 + sum1; mI1 = mn1;
#pragma unroll
        for (int nf = 0; nf < 8; nf++) {
            oacc[nf][0] *= c0; oacc[nf][1] *= c0;
            oacc[nf][2] *= c1; oacc[nf][3] *= c1;
        }

        // O += P @ V : P fragments directly from sa regs (RN fp16 pack),
        // V fragments via ldmatrix.trans from [kv][d] layout
        const uint32_t vsA = smb + (uint32_t)((3 + s) * KSTG) * 2;
#pragma unroll
        for (int ks = 0; ks < 4; ks++) {
            uint32_t pa0 = pack_h2(sa[2 * ks][0], sa[2 * ks][1]);
            uint32_t pa1 = pack_h2(sa[2 * ks][2], sa[2 * ks][3]);
            uint32_t pa2 = pack_h2(sa[2 * ks + 1][0], sa[2 * ks + 1][1]);
            uint32_t pa3 = pack_h2(sa[2 * ks + 1][2], sa[2 * ks + 1][3]);
#pragma unroll
            for (int p = 0; p < 4; p++) {
                uint32_t v0, v1, v2, v3;
                ldmx4t(v0, v1, v2, v3,
                       vsA + fvb + (uint32_t)((ks * 16 * FLDH + p * 16) * 2));
                mma_f16(oacc[2 * p], pa0, pa1, pa2, pa3, v0, v2);
                mma_f16(oacc[2 * p + 1], pa0, pa1, pa2, pa3, v1, v3);
            }
        }
    }

    // epilogue: normalize, fp16 RN, write [B*T, C]
    const float inv0 = 1.f / lI0, inv1 = 1.f / lI1;
    const int m0 = q0 + warp_m + lm;
    __half* ob0 = out + (size_t)(b * T_ + m0) * C_ + h * D_;
    __half* ob1 = out + (size_t)(b * T_ + m0 + 8) * C_ + h * D_;
#pragma unroll
    for (int nf = 0; nf < 8; nf++) {
        int cc = nf * 8 + 2 * lk;
        *(uint32_t*)(ob0 + cc) = pack_h2(oacc[nf][0] * inv0, oacc[nf][1] * inv0);
        *(uint32_t*)(ob1 + cc) = pack_h2(oacc[nf][2] * inv1, oacc[nf][3] * inv1);
    }
}

// ---------------------------------------------------------------------------
extern "C" void kernel_launch(void* const* d_in, const int* in_sizes, int n_in,
                              void* d_out, int out_size)
{
    const float* x     = (const float*)d_in[0];
    const float* w_qkv = (const float*)d_in[1];
    const float* w_out = (const float*)d_in[2];
    const float* b_out = (const float*)d_in[3];
    float* out = (float*)d_out;

    __half *qkv_p, *attn_p, *xh_p, *wqkvh_p, *wouth_p;
    cudaGetSymbolAddress((void**)&qkv_p, g_qkvh);
    cudaGetSymbolAddress((void**)&attn_p, g_attnh);
    cudaGetSymbolAddress((void**)&xh_p, g_xh);
    cudaGetSymbolAddress((void**)&wqkvh_p, g_wqkvh);
    cudaGetSymbolAddress((void**)&wouth_p, g_wouth);

    const int M = B_ * T_;

    // 0) fp32 -> fp16 (RTN)
    {
        int n8x = (M * C_) / 8;
        f32_to_f16_kernel<<<(n8x + 255) / 256, 256>>>((const float4*)x, (uint4*)xh_p, n8x);
        int n8w = (3 * C_ * C_) / 8;
        f32_to_f16_kernel<<<(n8w + 255) / 256, 256>>>((const float4*)w_qkv, (uint4*)wqkvh_p, n8w);
        int n8o = (C_ * C_) / 8;
        f32_to_f16_kernel<<<(n8o + 255) / 256, 256>>>((const float4*)w_out, (uint4*)wouth_p, n8o);
    }

    cudaFuncSetAttribute(gemm_mma_f16, cudaFuncAttributeMaxDynamicSharedMemorySize, G_SMEM);
    cudaFuncSetAttribute(flash_mma_f16, cudaFuncAttributeMaxDynamicSharedMemorySize, FSM_BYTES);

    // 1) qkv = x @ w_qkv^T  [8192, 3072] -> fp16
    {
        dim3 grid((3 * C_) / G_BN, M / G_BM);
        gemm_mma_f16<<<grid, 256, G_SMEM>>>(xh_p, wqkvh_p, nullptr, nullptr, qkv_p, 3 * C_, C_);
    }

    // 2) flash attention (fp16 mma + ldmatrix) -> g_attnh
    {
        dim3 grid(T_ / FBM, B_ * H_);
        flash_mma_f16<<<grid, 256, FSM_BYTES>>>(qkv_p, attn_p);
    }

    // 3) out = g_attn @ w_out^T + b_out  [8192, 1024] -> fp32
    {
        dim3 grid(C_ / G_BN, M / G_BM);
        gemm_mma_f16<<<grid, 256, G_SMEM>>>(attn_p, wouth_p, b_out, out, nullptr, C_, C_);
    }
}